// round 13
// baseline (speedup 1.0000x reference)
#include <cuda_runtime.h>
#include <cstdint>

#define NMAX   100000
#define EHMAX  1600000
#define HD     32          // hidden dim (Hemb == Hgcn == 32)
#define NIN    128
#define SCB    512                        // nodes per scan block
#define NSBMAX ((NMAX + SCB - 1) / SCB)   // scan blocks (196)

// ---------------- device scratch (no allocations allowed) ----------------
__device__ __align__(16) float g_h  [NMAX * HD];   // relu(x@We + be)
__device__ __align__(16) float g_hw [NMAX * HD];   // h@Wg (UNscaled; self term only)
__device__ __align__(8)  float2 g_tdis[NMAX];      // (t, rsqrt(deg+1)) packed
__device__ int   g_cnt [NMAX];        // degree counts   (self-cleaned by k_gather)
__device__ int   g_rel [NMAX];        // fill cursors    (self-cleaned by k_gather)
__device__ int   g_loc [NMAX];        // per-block exclusive prefix
__device__ int   g_bsum[NSBMAX];      // block sums
__device__ int   g_bpre[NSBMAX];      // scanned block sums (exclusive)
__device__ int   g_tick;              // last-block ticket (self-resetting)
__device__ int   g_adj [2 * EHMAX];   // CSR adjacency

__device__ __forceinline__ int ldcg_i(const int* p) {
    int v;
    asm volatile("ld.global.cg.s32 %0, [%1];" : "=r"(v) : "l"(p));
    return v;
}

// ---------------- K0: fused embed + degree count -------------------------
__global__ __launch_bounds__(256) void k_embed(
    const float* __restrict__ x, const float* __restrict__ We,
    const float* __restrict__ be, const float* __restrict__ Wg,
    const int* __restrict__ row, const int* __restrict__ col,
    int n, int eh)
{
    // prologue: degree counting over the undirected edge list
    {
        int gtid = blockIdx.x * 256 + threadIdx.x;
        int gstride = gridDim.x * 256;
        for (int e = gtid; e < eh; e += gstride) {
            atomicAdd(&g_cnt[row[e]], 1);
            atomicAdd(&g_cnt[col[e]], 1);
        }
    }

    __shared__ float sWe[NIN * HD];
    __shared__ float sWg[HD * HD];
    __shared__ float sbe[HD];
    __shared__ float sx[8][2][NIN];

    int tid = threadIdx.x;
    for (int i = tid; i < NIN * HD; i += 256) sWe[i] = We[i];
    for (int i = tid; i < HD * HD;  i += 256) sWg[i] = Wg[i];
    if (tid < HD) sbe[tid] = be[tid];
    __syncthreads();

    int warp = tid >> 5, j = tid & 31;
    int n0 = (blockIdx.x * 8 + warp) * 2;
    int n1 = n0 + 1;
    bool v0 = n0 < n, v1 = n1 < n;

    if (v0) {
        const float* xr = x + (size_t)n0 * NIN;
        sx[warp][0][j] = xr[j]; sx[warp][0][j+32] = xr[j+32];
        sx[warp][0][j+64] = xr[j+64]; sx[warp][0][j+96] = xr[j+96];
    }
    if (v1) {
        const float* xr = x + (size_t)n1 * NIN;
        sx[warp][1][j] = xr[j]; sx[warp][1][j+32] = xr[j+32];
        sx[warp][1][j+64] = xr[j+64]; sx[warp][1][j+96] = xr[j+96];
    } else {
        sx[warp][1][j] = 0.f; sx[warp][1][j+32] = 0.f;
        sx[warp][1][j+64] = 0.f; sx[warp][1][j+96] = 0.f;
    }
    __syncwarp();
    if (!v0) return;

    float a0 = sbe[j], a1 = sbe[j];
    #pragma unroll
    for (int k = 0; k < NIN; k++) {
        float w = sWe[k * HD + j];
        a0 = fmaf(sx[warp][0][k], w, a0);
        a1 = fmaf(sx[warp][1][k], w, a1);
    }
    float h0 = fmaxf(a0, 0.f), h1 = fmaxf(a1, 0.f);
    g_h[n0 * HD + j] = h0;
    if (v1) g_h[n1 * HD + j] = h1;

    float c0 = 0.f, c1 = 0.f;
    #pragma unroll
    for (int k = 0; k < HD; k++) {
        float w = sWg[k * HD + j];
        c0 = fmaf(__shfl_sync(0xffffffffu, h0, k), w, c0);
        c1 = fmaf(__shfl_sync(0xffffffffu, h1, k), w, c1);
    }
    g_hw[n0 * HD + j] = c0;
    if (v1) g_hw[n1 * HD + j] = c1;
}

// ---------------- K1: fused scan (local + last-block global) + tdis ------
__global__ __launch_bounds__(SCB) void k_scan(const float* __restrict__ t, int n, int nsb) {
    __shared__ int s[SCB];
    __shared__ int isLast;
    int tt = threadIdx.x;
    int i = blockIdx.x * SCB + tt;
    int v = (i < n) ? g_cnt[i] : 0;
    s[tt] = v;
    __syncthreads();
    #pragma unroll
    for (int off = 1; off < SCB; off <<= 1) {
        int xv = (tt >= off) ? s[tt - off] : 0;
        __syncthreads();
        s[tt] += xv;
        __syncthreads();
    }
    if (i < n) {
        g_loc[i] = s[tt] - v;                // exclusive
        g_tdis[i] = make_float2(t[i], rsqrtf((float)v + 1.0f));
    }
    if (tt == SCB - 1) g_bsum[blockIdx.x] = s[tt];

    __threadfence();
    if (tt == 0) isLast = (atomicAdd(&g_tick, 1) == gridDim.x - 1);
    __syncthreads();
    if (!isLast) return;

    // final block: scan the block sums (nsb <= SCB)
    int bv = (tt < nsb) ? ldcg_i(&g_bsum[tt]) : 0;
    s[tt] = bv;
    __syncthreads();
    #pragma unroll
    for (int off = 1; off < SCB; off <<= 1) {
        int xv = (tt >= off) ? s[tt - off] : 0;
        __syncthreads();
        s[tt] += xv;
        __syncthreads();
    }
    if (tt < nsb) g_bpre[tt] = s[tt] - bv;   // exclusive
    if (tt == 0) g_tick = 0;                 // self-reset for next call
}

// ---------------- K2: CSR fill — 4 edges/thread, 8 atomic chains --------
__global__ void k_fill(const int* __restrict__ row, const int* __restrict__ col, int eh) {
    int i = blockIdx.x * blockDim.x + threadIdx.x;
    int e0 = i * 4;
    if (e0 >= eh) return;
    if (e0 + 3 < eh) {
        int4 rr = ((const int4*)row)[i];
        int4 cc = ((const int4*)col)[i];
        int ps0 = g_loc[rr.x] + g_bpre[rr.x >> 9] + atomicAdd(&g_rel[rr.x], 1);
        int pd0 = g_loc[cc.x] + g_bpre[cc.x >> 9] + atomicAdd(&g_rel[cc.x], 1);
        int ps1 = g_loc[rr.y] + g_bpre[rr.y >> 9] + atomicAdd(&g_rel[rr.y], 1);
        int pd1 = g_loc[cc.y] + g_bpre[cc.y >> 9] + atomicAdd(&g_rel[cc.y], 1);
        int ps2 = g_loc[rr.z] + g_bpre[rr.z >> 9] + atomicAdd(&g_rel[rr.z], 1);
        int pd2 = g_loc[cc.z] + g_bpre[cc.z >> 9] + atomicAdd(&g_rel[cc.z], 1);
        int ps3 = g_loc[rr.w] + g_bpre[rr.w >> 9] + atomicAdd(&g_rel[rr.w], 1);
        int pd3 = g_loc[cc.w] + g_bpre[cc.w >> 9] + atomicAdd(&g_rel[cc.w], 1);
        g_adj[ps0] = cc.x;  g_adj[pd0] = rr.x;
        g_adj[ps1] = cc.y;  g_adj[pd1] = rr.y;
        g_adj[ps2] = cc.z;  g_adj[pd2] = rr.z;
        g_adj[ps3] = cc.w;  g_adj[pd3] = rr.w;
    } else {
        for (int e = e0; e < eh; e++) {
            int s = row[e], d = col[e];
            int ps = g_loc[s] + g_bpre[s >> 9] + atomicAdd(&g_rel[s], 1);
            g_adj[ps] = d;
            int pd = g_loc[d] + g_bpre[d >> 9] + atomicAdd(&g_rel[d], 1);
            g_adj[pd] = s;
        }
    }
}

// ---------------- K3: fused gather + final ------------------------------
// Warp per node. sub = lane&7 (float4 slot), g = lane>>3 (neighbor group).
// SINGLE gather stream: h[v] only. GCN agg uses linearity:
//   agg_i = (sum_v dis_v*h_v) @ Wg     (Wg applied once per node at end)
// so the hw[v] gather stream is eliminated. (t,dis) packed in one float2.
__global__ __launch_bounds__(256, 6) void k_gather(
    const float* __restrict__ Wgm,
    const float* __restrict__ W1, const float* __restrict__ b1,
    const float* __restrict__ W2, const float* __restrict__ b2,
    const float* __restrict__ b_gcn,
    float* __restrict__ outp, float* __restrict__ repp, float* __restrict__ zoutp,
    int n)
{
    __shared__ float sW1[34 * HD];
    __shared__ float sWg[HD * HD];
    __shared__ float sb1[HD], sW2[HD], sb2s[1];
    __shared__ float sAcc[8][128];            // per-warp float4 transpose buffer

    int tid = threadIdx.x;
    for (int i = tid; i < 34 * HD; i += 256) sW1[i] = W1[i];
    for (int i = tid; i < HD * HD;  i += 256) sWg[i] = Wgm[i];
    if (tid < HD) { sb1[tid] = b1[tid]; sW2[tid] = W2[tid]; }
    if (tid == 0) sb2s[0] = b2[0];
    __syncthreads();

    int warp = tid >> 5, lane = tid & 31;
    int node = blockIdx.x * 8 + warp;
    if (node >= n) return;

    int sub = lane & 7;
    int g   = lane >> 3;
    unsigned gmask = 0xFFu << (g * 8);

    const float4* h4 = (const float4*)g_h;

    float4 hi = h4[(size_t)node * 8 + sub];
    int off = g_loc[node] + g_bpre[node >> 9];
    int cnt = g_cnt[node];

    // self-clean CSR state for the next kernel_launch call
    if (lane == 0) { g_cnt[node] = 0; g_rel[node] = 0; }

    float4 acc = make_float4(0.f, 0.f, 0.f, 0.f);  // sum dis_v * h_v
    float deno = 0.f, z = 0.f;

    int k = g;
    for (; k + 4 < cnt; k += 8) {
        int v0 = g_adj[off + k];
        int v1 = g_adj[off + k + 4];
        float4 hv0 = h4[(size_t)v0 * 8 + sub];
        float4 hv1 = h4[(size_t)v1 * 8 + sub];
        float2 td0 = g_tdis[v0];
        float2 td1 = g_tdis[v1];

        float p0 = hi.x*hv0.x + hi.y*hv0.y + hi.z*hv0.z + hi.w*hv0.w;
        float p1 = hi.x*hv1.x + hi.y*hv1.y + hi.z*hv1.z + hi.w*hv1.w;
        p0 += __shfl_xor_sync(gmask, p0, 1);
        p1 += __shfl_xor_sync(gmask, p1, 1);
        p0 += __shfl_xor_sync(gmask, p0, 2);
        p1 += __shfl_xor_sync(gmask, p1, 2);
        p0 += __shfl_xor_sync(gmask, p0, 4);
        p1 += __shfl_xor_sync(gmask, p1, 4);
        float a0 = __expf(p0);
        float a1 = __expf(p1);
        deno += a0 + a1;
        z = fmaf(a0, td0.x, z);
        z = fmaf(a1, td1.x, z);
        acc.x = fmaf(td0.y, hv0.x, acc.x); acc.x = fmaf(td1.y, hv1.x, acc.x);
        acc.y = fmaf(td0.y, hv0.y, acc.y); acc.y = fmaf(td1.y, hv1.y, acc.y);
        acc.z = fmaf(td0.y, hv0.z, acc.z); acc.z = fmaf(td1.y, hv1.z, acc.z);
        acc.w = fmaf(td0.y, hv0.w, acc.w); acc.w = fmaf(td1.y, hv1.w, acc.w);
    }
    if (k < cnt) {  // at most one remainder per group
        int v = g_adj[off + k];
        float4 hv = h4[(size_t)v * 8 + sub];
        float2 td = g_tdis[v];
        float p = hi.x*hv.x + hi.y*hv.y + hi.z*hv.z + hi.w*hv.w;
        p += __shfl_xor_sync(gmask, p, 1);
        p += __shfl_xor_sync(gmask, p, 2);
        p += __shfl_xor_sync(gmask, p, 4);
        float a = __expf(p);
        deno += a;
        z = fmaf(a, td.x, z);
        acc.x = fmaf(td.y, hv.x, acc.x);
        acc.y = fmaf(td.y, hv.y, acc.y);
        acc.z = fmaf(td.y, hv.z, acc.z);
        acc.w = fmaf(td.y, hv.w, acc.w);
    }

    // deno/z: 8 lanes of each group hold identical partials -> warp tree
    // sum = 8 * (sum over groups); *0.125f is exact (power of two).
    #pragma unroll
    for (int o = 1; o < 32; o <<= 1) {
        deno += __shfl_xor_sync(0xffffffffu, deno, o);
        z    += __shfl_xor_sync(0xffffffffu, z,    o);
    }
    deno *= 0.125f; z *= 0.125f;

    // transpose acc (float4-per-lane) -> scalar-per-feature via smem
    sAcc[warp][lane * 4 + 0] = acc.x;
    sAcc[warp][lane * 4 + 1] = acc.y;
    sAcc[warp][lane * 4 + 2] = acc.z;
    sAcc[warp][lane * 4 + 3] = acc.w;
    __syncwarp();
    int slot = lane >> 2, comp = lane & 3;
    float aggj = 0.f;
    #pragma unroll
    for (int gg = 0; gg < 4; gg++)
        aggj += sAcc[warp][(gg * 8 + slot) * 4 + comp];
    // aggj = (sum_v dis_v h_v)[feature lane]; apply Wg: aggw = agg @ Wg
    float aggw = 0.f;
    #pragma unroll
    for (int kk = 0; kk < HD; kk++)
        aggw = fmaf(__shfl_sync(0xffffffffu, aggj, kk), sWg[kk * HD + lane], aggw);

    // ---- final head, inline ----
    float2 tdn = g_tdis[node];
    float dis = tdn.y;
    float hwj = g_hw[(size_t)node * HD + lane];   // h@Wg, UNscaled
    float hj  = g_h [(size_t)node * HD + lane];
    float gcn = dis * aggw + (dis * dis) * hwj + b_gcn[lane];
    float rep = hj + fmaxf(gcn, 0.f);
    if (repp) repp[(size_t)node * HD + lane] = rep;

    float zi = z / (deno + 1e-8f);
    float ti = tdn.x;

    float accm = sb1[lane];
    #pragma unroll
    for (int kk = 0; kk < HD; kk++)
        accm = fmaf(__shfl_sync(0xffffffffu, rep, kk), sW1[kk * HD + lane], accm);
    accm = fmaf(ti, sW1[32 * HD + lane], accm);
    accm = fmaf(zi, sW1[33 * HD + lane], accm);
    accm = fmaxf(accm, 0.f);

    float o = accm * sW2[lane];
    #pragma unroll
    for (int offr = 16; offr > 0; offr >>= 1)
        o += __shfl_xor_sync(0xffffffffu, o, offr);
    if (lane == 0) outp[node] = o + sb2s[0];
    if (zoutp && lane == 1) zoutp[node] = zi;
}

// ---------------- host ----------------
extern "C" void kernel_launch(void* const* d_in, const int* in_sizes, int n_in,
                              void* d_out, int out_size)
{
    const float* x     = (const float*)d_in[0];
    const float* t     = (const float*)d_in[1];
    const int*   row   = (const int*)  d_in[2];
    const int*   col   = (const int*)  d_in[3];
    const float* W_emb = (const float*)d_in[4];
    const float* b_emb = (const float*)d_in[5];
    const float* W_gcn = (const float*)d_in[6];
    const float* b_gcn = (const float*)d_in[7];
    const float* W1    = (const float*)d_in[8];
    const float* b1    = (const float*)d_in[9];
    const float* W2    = (const float*)d_in[10];
    const float* b2    = (const float*)d_in[11];

    int n  = in_sizes[1];          // t has N elements
    int e2 = in_sizes[2];          // full directed edge count
    int eh = e2 / 2;               // symmetric half
    int nsb = (n + SCB - 1) / SCB;

    float* outp = (float*)d_out;
    bool full = (out_size == 34 * n);
    float* repp  = full ? outp + n      : nullptr;
    float* zoutp = full ? outp + 33 * n : nullptr;

    k_embed <<<(n + 15) / 16, 256>>>(x, W_emb, b_emb, W_gcn, row, col, n, eh); // idx 0
    k_scan  <<<nsb, SCB>>>(t, n, nsb);                                         // idx 1
    k_fill  <<<(eh + 1023) / 1024, 256>>>(row, col, eh);                       // idx 2
    k_gather<<<(n + 7) / 8, 256>>>(W_gcn, W1, b1, W2, b2, b_gcn, outp, repp, zoutp, n); // idx 3 (ncu)
}

// round 14
// speedup vs baseline: 1.0996x; 1.0996x over previous
#include <cuda_runtime.h>
#include <cstdint>

#define NMAX   100000
#define EHMAX  1600000
#define HD     32          // hidden dim (Hemb == Hgcn == 32)
#define NIN    128
#define SCB    512                        // nodes per scan block
#define NSBMAX ((NMAX + SCB - 1) / SCB)   // scan blocks (196)

// ---------------- device scratch (no allocations allowed) ----------------
__device__ __align__(16) float g_h  [NMAX * HD];   // relu(x@We + be)
__device__ __align__(16) float g_hw [NMAX * HD];   // h@Wg (UNscaled; self term only)
__device__ __align__(8)  float2 g_tdis[NMAX];      // (t, rsqrt(deg+1)) packed
__device__ int   g_cnt [NMAX];        // degree counts   (self-cleaned by k_gather)
__device__ int   g_rel [NMAX];        // fill cursors    (self-cleaned by k_gather)
__device__ int   g_loc [NMAX];        // per-block exclusive prefix
__device__ int   g_bsum[NSBMAX];      // block sums
__device__ int   g_bpre[NSBMAX];      // scanned block sums (exclusive)
__device__ int   g_tick;              // last-block ticket (self-resetting)
__device__ int   g_adj [2 * EHMAX];   // CSR adjacency

__device__ __forceinline__ int ldcg_i(const int* p) {
    int v;
    asm volatile("ld.global.cg.s32 %0, [%1];" : "=r"(v) : "l"(p));
    return v;
}

// ---------------- K0: fused embed + degree count -------------------------
__global__ __launch_bounds__(256) void k_embed(
    const float* __restrict__ x, const float* __restrict__ We,
    const float* __restrict__ be, const float* __restrict__ Wg,
    const int* __restrict__ row, const int* __restrict__ col,
    int n, int eh)
{
    // prologue: degree counting over the undirected edge list
    {
        int gtid = blockIdx.x * 256 + threadIdx.x;
        int gstride = gridDim.x * 256;
        for (int e = gtid; e < eh; e += gstride) {
            atomicAdd(&g_cnt[row[e]], 1);
            atomicAdd(&g_cnt[col[e]], 1);
        }
    }

    __shared__ float sWe[NIN * HD];
    __shared__ float sWg[HD * HD];
    __shared__ float sbe[HD];
    __shared__ float sx[8][2][NIN];

    int tid = threadIdx.x;
    for (int i = tid; i < NIN * HD; i += 256) sWe[i] = We[i];
    for (int i = tid; i < HD * HD;  i += 256) sWg[i] = Wg[i];
    if (tid < HD) sbe[tid] = be[tid];
    __syncthreads();

    int warp = tid >> 5, j = tid & 31;
    int n0 = (blockIdx.x * 8 + warp) * 2;
    int n1 = n0 + 1;
    bool v0 = n0 < n, v1 = n1 < n;

    if (v0) {
        const float* xr = x + (size_t)n0 * NIN;
        sx[warp][0][j] = xr[j]; sx[warp][0][j+32] = xr[j+32];
        sx[warp][0][j+64] = xr[j+64]; sx[warp][0][j+96] = xr[j+96];
    }
    if (v1) {
        const float* xr = x + (size_t)n1 * NIN;
        sx[warp][1][j] = xr[j]; sx[warp][1][j+32] = xr[j+32];
        sx[warp][1][j+64] = xr[j+64]; sx[warp][1][j+96] = xr[j+96];
    } else {
        sx[warp][1][j] = 0.f; sx[warp][1][j+32] = 0.f;
        sx[warp][1][j+64] = 0.f; sx[warp][1][j+96] = 0.f;
    }
    __syncwarp();
    if (!v0) return;

    float a0 = sbe[j], a1 = sbe[j];
    #pragma unroll
    for (int k = 0; k < NIN; k++) {
        float w = sWe[k * HD + j];
        a0 = fmaf(sx[warp][0][k], w, a0);
        a1 = fmaf(sx[warp][1][k], w, a1);
    }
    float h0 = fmaxf(a0, 0.f), h1 = fmaxf(a1, 0.f);
    g_h[n0 * HD + j] = h0;
    if (v1) g_h[n1 * HD + j] = h1;

    float c0 = 0.f, c1 = 0.f;
    #pragma unroll
    for (int k = 0; k < HD; k++) {
        float w = sWg[k * HD + j];
        c0 = fmaf(__shfl_sync(0xffffffffu, h0, k), w, c0);
        c1 = fmaf(__shfl_sync(0xffffffffu, h1, k), w, c1);
    }
    g_hw[n0 * HD + j] = c0;
    if (v1) g_hw[n1 * HD + j] = c1;
}

// ---------------- K1: fused scan (local + last-block global) + tdis ------
__global__ __launch_bounds__(SCB) void k_scan(const float* __restrict__ t, int n, int nsb) {
    __shared__ int s[SCB];
    __shared__ int isLast;
    int tt = threadIdx.x;
    int i = blockIdx.x * SCB + tt;
    int v = (i < n) ? g_cnt[i] : 0;
    s[tt] = v;
    __syncthreads();
    #pragma unroll
    for (int off = 1; off < SCB; off <<= 1) {
        int xv = (tt >= off) ? s[tt - off] : 0;
        __syncthreads();
        s[tt] += xv;
        __syncthreads();
    }
    if (i < n) {
        g_loc[i] = s[tt] - v;                // exclusive
        g_tdis[i] = make_float2(t[i], rsqrtf((float)v + 1.0f));
    }
    if (tt == SCB - 1) g_bsum[blockIdx.x] = s[tt];

    __threadfence();
    if (tt == 0) isLast = (atomicAdd(&g_tick, 1) == gridDim.x - 1);
    __syncthreads();
    if (!isLast) return;

    // final block: scan the block sums (nsb <= SCB)
    int bv = (tt < nsb) ? ldcg_i(&g_bsum[tt]) : 0;
    s[tt] = bv;
    __syncthreads();
    #pragma unroll
    for (int off = 1; off < SCB; off <<= 1) {
        int xv = (tt >= off) ? s[tt - off] : 0;
        __syncthreads();
        s[tt] += xv;
        __syncthreads();
    }
    if (tt < nsb) g_bpre[tt] = s[tt] - bv;   // exclusive
    if (tt == 0) g_tick = 0;                 // self-reset for next call
}

// ---------------- K2: CSR fill — 4 edges/thread, 8 atomic chains --------
__global__ void k_fill(const int* __restrict__ row, const int* __restrict__ col, int eh) {
    int i = blockIdx.x * blockDim.x + threadIdx.x;
    int e0 = i * 4;
    if (e0 >= eh) return;
    if (e0 + 3 < eh) {
        int4 rr = ((const int4*)row)[i];
        int4 cc = ((const int4*)col)[i];
        int ps0 = g_loc[rr.x] + g_bpre[rr.x >> 9] + atomicAdd(&g_rel[rr.x], 1);
        int pd0 = g_loc[cc.x] + g_bpre[cc.x >> 9] + atomicAdd(&g_rel[cc.x], 1);
        int ps1 = g_loc[rr.y] + g_bpre[rr.y >> 9] + atomicAdd(&g_rel[rr.y], 1);
        int pd1 = g_loc[cc.y] + g_bpre[cc.y >> 9] + atomicAdd(&g_rel[cc.y], 1);
        int ps2 = g_loc[rr.z] + g_bpre[rr.z >> 9] + atomicAdd(&g_rel[rr.z], 1);
        int pd2 = g_loc[cc.z] + g_bpre[cc.z >> 9] + atomicAdd(&g_rel[cc.z], 1);
        int ps3 = g_loc[rr.w] + g_bpre[rr.w >> 9] + atomicAdd(&g_rel[rr.w], 1);
        int pd3 = g_loc[cc.w] + g_bpre[cc.w >> 9] + atomicAdd(&g_rel[cc.w], 1);
        g_adj[ps0] = cc.x;  g_adj[pd0] = rr.x;
        g_adj[ps1] = cc.y;  g_adj[pd1] = rr.y;
        g_adj[ps2] = cc.z;  g_adj[pd2] = rr.z;
        g_adj[ps3] = cc.w;  g_adj[pd3] = rr.w;
    } else {
        for (int e = e0; e < eh; e++) {
            int s = row[e], d = col[e];
            int ps = g_loc[s] + g_bpre[s >> 9] + atomicAdd(&g_rel[s], 1);
            g_adj[ps] = d;
            int pd = g_loc[d] + g_bpre[d >> 9] + atomicAdd(&g_rel[d], 1);
            g_adj[pd] = s;
        }
    }
}

// ---------------- K3: fused gather + final ------------------------------
// Warp per node. sub = lane&7 (float4 slot), g = lane>>3 (neighbor group).
// SINGLE gather stream: h[v] only (GCN agg via linearity, Wg applied once
// per node). minBlocks=5 (NOT 6): R13 showed the 40-reg cap forces local
// spills in the hot loop (+60us); the optimum is ~46 regs @ 5 blocks.
__global__ __launch_bounds__(256, 5) void k_gather(
    const float* __restrict__ Wgm,
    const float* __restrict__ W1, const float* __restrict__ b1,
    const float* __restrict__ W2, const float* __restrict__ b2,
    const float* __restrict__ b_gcn,
    float* __restrict__ outp, float* __restrict__ repp, float* __restrict__ zoutp,
    int n)
{
    __shared__ float sW1[34 * HD];
    __shared__ float sWg[HD * HD];
    __shared__ float sb1[HD], sW2[HD], sb2s[1];
    __shared__ float sAcc[8][128];            // per-warp float4 transpose buffer

    int tid = threadIdx.x;
    for (int i = tid; i < 34 * HD; i += 256) sW1[i] = W1[i];
    for (int i = tid; i < HD * HD;  i += 256) sWg[i] = Wgm[i];
    if (tid < HD) { sb1[tid] = b1[tid]; sW2[tid] = W2[tid]; }
    if (tid == 0) sb2s[0] = b2[0];
    __syncthreads();

    int warp = tid >> 5, lane = tid & 31;
    int node = blockIdx.x * 8 + warp;
    if (node >= n) return;

    int sub = lane & 7;
    int g   = lane >> 3;
    unsigned gmask = 0xFFu << (g * 8);

    const float4* h4 = (const float4*)g_h;

    float4 hi = h4[(size_t)node * 8 + sub];
    int off = g_loc[node] + g_bpre[node >> 9];
    int cnt = g_cnt[node];

    // self-clean CSR state for the next kernel_launch call
    if (lane == 0) { g_cnt[node] = 0; g_rel[node] = 0; }

    float4 acc = make_float4(0.f, 0.f, 0.f, 0.f);  // sum dis_v * h_v
    float deno = 0.f, z = 0.f;

    int k = g;
    for (; k + 4 < cnt; k += 8) {
        int v0 = g_adj[off + k];
        int v1 = g_adj[off + k + 4];
        float4 hv0 = h4[(size_t)v0 * 8 + sub];
        float4 hv1 = h4[(size_t)v1 * 8 + sub];
        float2 td0 = g_tdis[v0];
        float2 td1 = g_tdis[v1];

        float p0 = hi.x*hv0.x + hi.y*hv0.y + hi.z*hv0.z + hi.w*hv0.w;
        float p1 = hi.x*hv1.x + hi.y*hv1.y + hi.z*hv1.z + hi.w*hv1.w;
        p0 += __shfl_xor_sync(gmask, p0, 1);
        p1 += __shfl_xor_sync(gmask, p1, 1);
        p0 += __shfl_xor_sync(gmask, p0, 2);
        p1 += __shfl_xor_sync(gmask, p1, 2);
        p0 += __shfl_xor_sync(gmask, p0, 4);
        p1 += __shfl_xor_sync(gmask, p1, 4);
        float a0 = __expf(p0);
        float a1 = __expf(p1);
        deno += a0 + a1;
        z = fmaf(a0, td0.x, z);
        z = fmaf(a1, td1.x, z);
        acc.x = fmaf(td0.y, hv0.x, acc.x); acc.x = fmaf(td1.y, hv1.x, acc.x);
        acc.y = fmaf(td0.y, hv0.y, acc.y); acc.y = fmaf(td1.y, hv1.y, acc.y);
        acc.z = fmaf(td0.y, hv0.z, acc.z); acc.z = fmaf(td1.y, hv1.z, acc.z);
        acc.w = fmaf(td0.y, hv0.w, acc.w); acc.w = fmaf(td1.y, hv1.w, acc.w);
    }
    if (k < cnt) {  // at most one remainder per group
        int v = g_adj[off + k];
        float4 hv = h4[(size_t)v * 8 + sub];
        float2 td = g_tdis[v];
        float p = hi.x*hv.x + hi.y*hv.y + hi.z*hv.z + hi.w*hv.w;
        p += __shfl_xor_sync(gmask, p, 1);
        p += __shfl_xor_sync(gmask, p, 2);
        p += __shfl_xor_sync(gmask, p, 4);
        float a = __expf(p);
        deno += a;
        z = fmaf(a, td.x, z);
        acc.x = fmaf(td.y, hv.x, acc.x);
        acc.y = fmaf(td.y, hv.y, acc.y);
        acc.z = fmaf(td.y, hv.z, acc.z);
        acc.w = fmaf(td.y, hv.w, acc.w);
    }

    // deno/z: 8 lanes of each group hold identical partials -> warp tree
    // sum = 8 * (sum over groups); *0.125f is exact (power of two).
    #pragma unroll
    for (int o = 1; o < 32; o <<= 1) {
        deno += __shfl_xor_sync(0xffffffffu, deno, o);
        z    += __shfl_xor_sync(0xffffffffu, z,    o);
    }
    deno *= 0.125f; z *= 0.125f;

    // transpose acc (float4-per-lane) -> scalar-per-feature via smem
    sAcc[warp][lane * 4 + 0] = acc.x;
    sAcc[warp][lane * 4 + 1] = acc.y;
    sAcc[warp][lane * 4 + 2] = acc.z;
    sAcc[warp][lane * 4 + 3] = acc.w;
    __syncwarp();
    int slot = lane >> 2, comp = lane & 3;
    float aggj = 0.f;
    #pragma unroll
    for (int gg = 0; gg < 4; gg++)
        aggj += sAcc[warp][(gg * 8 + slot) * 4 + comp];
    // aggj = (sum_v dis_v h_v)[feature lane]; apply Wg: aggw = agg @ Wg
    float aggw = 0.f;
    #pragma unroll
    for (int kk = 0; kk < HD; kk++)
        aggw = fmaf(__shfl_sync(0xffffffffu, aggj, kk), sWg[kk * HD + lane], aggw);

    // ---- final head, inline ----
    float2 tdn = g_tdis[node];
    float dis = tdn.y;
    float hwj = g_hw[(size_t)node * HD + lane];   // h@Wg, UNscaled
    float hj  = g_h [(size_t)node * HD + lane];
    float gcn = dis * aggw + (dis * dis) * hwj + b_gcn[lane];
    float rep = hj + fmaxf(gcn, 0.f);
    if (repp) repp[(size_t)node * HD + lane] = rep;

    float zi = z / (deno + 1e-8f);
    float ti = tdn.x;

    float accm = sb1[lane];
    #pragma unroll
    for (int kk = 0; kk < HD; kk++)
        accm = fmaf(__shfl_sync(0xffffffffu, rep, kk), sW1[kk * HD + lane], accm);
    accm = fmaf(ti, sW1[32 * HD + lane], accm);
    accm = fmaf(zi, sW1[33 * HD + lane], accm);
    accm = fmaxf(accm, 0.f);

    float o = accm * sW2[lane];
    #pragma unroll
    for (int offr = 16; offr > 0; offr >>= 1)
        o += __shfl_xor_sync(0xffffffffu, o, offr);
    if (lane == 0) outp[node] = o + sb2s[0];
    if (zoutp && lane == 1) zoutp[node] = zi;
}

// ---------------- host ----------------
extern "C" void kernel_launch(void* const* d_in, const int* in_sizes, int n_in,
                              void* d_out, int out_size)
{
    const float* x     = (const float*)d_in[0];
    const float* t     = (const float*)d_in[1];
    const int*   row   = (const int*)  d_in[2];
    const int*   col   = (const int*)  d_in[3];
    const float* W_emb = (const float*)d_in[4];
    const float* b_emb = (const float*)d_in[5];
    const float* W_gcn = (const float*)d_in[6];
    const float* b_gcn = (const float*)d_in[7];
    const float* W1    = (const float*)d_in[8];
    const float* b1    = (const float*)d_in[9];
    const float* W2    = (const float*)d_in[10];
    const float* b2    = (const float*)d_in[11];

    int n  = in_sizes[1];          // t has N elements
    int e2 = in_sizes[2];          // full directed edge count
    int eh = e2 / 2;               // symmetric half
    int nsb = (n + SCB - 1) / SCB;

    float* outp = (float*)d_out;
    bool full = (out_size == 34 * n);
    float* repp  = full ? outp + n      : nullptr;
    float* zoutp = full ? outp + 33 * n : nullptr;

    k_embed <<<(n + 15) / 16, 256>>>(x, W_emb, b_emb, W_gcn, row, col, n, eh); // idx 0
    k_scan  <<<nsb, SCB>>>(t, n, nsb);                                         // idx 1
    k_fill  <<<(eh + 1023) / 1024, 256>>>(row, col, eh);                       // idx 2
    k_gather<<<(n + 7) / 8, 256>>>(W_gcn, W1, b1, W2, b2, b_gcn, outp, repp, zoutp, n); // idx 3 (ncu)
}

// round 15
// speedup vs baseline: 1.1578x; 1.0529x over previous
#include <cuda_runtime.h>
#include <cstdint>

#define NMAX   100000
#define EHMAX  1600000
#define HD     32          // hidden dim (Hemb == Hgcn == 32)
#define NIN    128
#define SCB    512                        // nodes per scan block
#define NSBMAX ((NMAX + SCB - 1) / SCB)   // scan blocks (196)

// ---------------- device scratch (no allocations allowed) ----------------
__device__ __align__(16) float g_h  [NMAX * HD];   // relu(x@We + be)
__device__ __align__(16) float g_hd [NMAX * HD];   // dis * h  (gather stream)
__device__ __align__(16) float g_hw [NMAX * HD];   // h@Wg (UNscaled; self term)
__device__ __align__(8)  float2 g_tdis[NMAX];      // (t, sqrt(deg+1)=1/dis)
__device__ int   g_cnt [NMAX];        // degree counts   (self-cleaned by k_gather)
__device__ int   g_rel [NMAX];        // fill cursors    (self-cleaned by k_gather)
__device__ int   g_loc [NMAX];        // per-block exclusive prefix
__device__ int   g_bsum[NSBMAX];      // block sums
__device__ int   g_bpre[NSBMAX];      // scanned block sums (exclusive)
__device__ int   g_tick;              // last-block ticket (self-resetting)
__device__ int   g_adj [2 * EHMAX];   // CSR adjacency

__device__ __forceinline__ int ldcg_i(const int* p) {
    int v;
    asm volatile("ld.global.cg.s32 %0, [%1];" : "=r"(v) : "l"(p));
    return v;
}

// ---------------- K0: fused embed + degree count -------------------------
__global__ __launch_bounds__(256) void k_embed(
    const float* __restrict__ x, const float* __restrict__ We,
    const float* __restrict__ be, const float* __restrict__ Wg,
    const int* __restrict__ row, const int* __restrict__ col,
    int n, int eh)
{
    // prologue: degree counting over the undirected edge list
    {
        int gtid = blockIdx.x * 256 + threadIdx.x;
        int gstride = gridDim.x * 256;
        for (int e = gtid; e < eh; e += gstride) {
            atomicAdd(&g_cnt[row[e]], 1);
            atomicAdd(&g_cnt[col[e]], 1);
        }
    }

    __shared__ float sWe[NIN * HD];
    __shared__ float sWg[HD * HD];
    __shared__ float sbe[HD];
    __shared__ float sx[8][2][NIN];

    int tid = threadIdx.x;
    for (int i = tid; i < NIN * HD; i += 256) sWe[i] = We[i];
    for (int i = tid; i < HD * HD;  i += 256) sWg[i] = Wg[i];
    if (tid < HD) sbe[tid] = be[tid];
    __syncthreads();

    int warp = tid >> 5, j = tid & 31;
    int n0 = (blockIdx.x * 8 + warp) * 2;
    int n1 = n0 + 1;
    bool v0 = n0 < n, v1 = n1 < n;

    if (v0) {
        const float* xr = x + (size_t)n0 * NIN;
        sx[warp][0][j] = xr[j]; sx[warp][0][j+32] = xr[j+32];
        sx[warp][0][j+64] = xr[j+64]; sx[warp][0][j+96] = xr[j+96];
    }
    if (v1) {
        const float* xr = x + (size_t)n1 * NIN;
        sx[warp][1][j] = xr[j]; sx[warp][1][j+32] = xr[j+32];
        sx[warp][1][j+64] = xr[j+64]; sx[warp][1][j+96] = xr[j+96];
    } else {
        sx[warp][1][j] = 0.f; sx[warp][1][j+32] = 0.f;
        sx[warp][1][j+64] = 0.f; sx[warp][1][j+96] = 0.f;
    }
    __syncwarp();
    if (!v0) return;

    float a0 = sbe[j], a1 = sbe[j];
    #pragma unroll
    for (int k = 0; k < NIN; k++) {
        float w = sWe[k * HD + j];
        a0 = fmaf(sx[warp][0][k], w, a0);
        a1 = fmaf(sx[warp][1][k], w, a1);
    }
    float h0 = fmaxf(a0, 0.f), h1 = fmaxf(a1, 0.f);
    g_h[n0 * HD + j] = h0;
    if (v1) g_h[n1 * HD + j] = h1;

    float c0 = 0.f, c1 = 0.f;
    #pragma unroll
    for (int k = 0; k < HD; k++) {
        float w = sWg[k * HD + j];
        c0 = fmaf(__shfl_sync(0xffffffffu, h0, k), w, c0);
        c1 = fmaf(__shfl_sync(0xffffffffu, h1, k), w, c1);
    }
    g_hw[n0 * HD + j] = c0;
    if (v1) g_hw[n1 * HD + j] = c1;
}

// ---------------- K1: fused scan + tdis + hd = dis*h ---------------------
__global__ __launch_bounds__(SCB) void k_scan(const float* __restrict__ t, int n, int nsb) {
    __shared__ int s[SCB];
    __shared__ int isLast;
    int tt = threadIdx.x;
    int i = blockIdx.x * SCB + tt;
    int v = (i < n) ? g_cnt[i] : 0;
    s[tt] = v;
    __syncthreads();
    #pragma unroll
    for (int off = 1; off < SCB; off <<= 1) {
        int xv = (tt >= off) ? s[tt - off] : 0;
        __syncthreads();
        s[tt] += xv;
        __syncthreads();
    }
    if (i < n) {
        g_loc[i] = s[tt] - v;                // exclusive
        g_tdis[i] = make_float2(t[i], sqrtf((float)v + 1.0f));  // (t, 1/dis)
    }
    if (tt == SCB - 1) g_bsum[blockIdx.x] = s[tt];

    // hd = dis * h for this block's nodes (block-strided float4)
    {
        const float4* h4p = (const float4*)g_h;
        float4* hd4p = (float4*)g_hd;
        int base4 = blockIdx.x * SCB * 8;
        #pragma unroll
        for (int q = 0; q < 8; q++) {
            int idx = base4 + q * SCB + tt;
            if (idx < n * 8) {
                int nd = idx >> 3;
                float ds = rsqrtf((float)g_cnt[nd] + 1.0f);
                float4 w = h4p[idx];
                w.x *= ds; w.y *= ds; w.z *= ds; w.w *= ds;
                hd4p[idx] = w;
            }
        }
    }

    __threadfence();
    if (tt == 0) isLast = (atomicAdd(&g_tick, 1) == gridDim.x - 1);
    __syncthreads();
    if (!isLast) return;

    // final block: scan the block sums (nsb <= SCB)
    int bv = (tt < nsb) ? ldcg_i(&g_bsum[tt]) : 0;
    s[tt] = bv;
    __syncthreads();
    #pragma unroll
    for (int off = 1; off < SCB; off <<= 1) {
        int xv = (tt >= off) ? s[tt - off] : 0;
        __syncthreads();
        s[tt] += xv;
        __syncthreads();
    }
    if (tt < nsb) g_bpre[tt] = s[tt] - bv;   // exclusive
    if (tt == 0) g_tick = 0;                 // self-reset for next call
}

// ---------------- K2: CSR fill — 4 edges/thread, 8 atomic chains --------
__global__ void k_fill(const int* __restrict__ row, const int* __restrict__ col, int eh) {
    int i = blockIdx.x * blockDim.x + threadIdx.x;
    int e0 = i * 4;
    if (e0 >= eh) return;
    if (e0 + 3 < eh) {
        int4 rr = ((const int4*)row)[i];
        int4 cc = ((const int4*)col)[i];
        int ps0 = g_loc[rr.x] + g_bpre[rr.x >> 9] + atomicAdd(&g_rel[rr.x], 1);
        int pd0 = g_loc[cc.x] + g_bpre[cc.x >> 9] + atomicAdd(&g_rel[cc.x], 1);
        int ps1 = g_loc[rr.y] + g_bpre[rr.y >> 9] + atomicAdd(&g_rel[rr.y], 1);
        int pd1 = g_loc[cc.y] + g_bpre[cc.y >> 9] + atomicAdd(&g_rel[cc.y], 1);
        int ps2 = g_loc[rr.z] + g_bpre[rr.z >> 9] + atomicAdd(&g_rel[rr.z], 1);
        int pd2 = g_loc[cc.z] + g_bpre[cc.z >> 9] + atomicAdd(&g_rel[cc.z], 1);
        int ps3 = g_loc[rr.w] + g_bpre[rr.w >> 9] + atomicAdd(&g_rel[rr.w], 1);
        int pd3 = g_loc[cc.w] + g_bpre[cc.w >> 9] + atomicAdd(&g_rel[cc.w], 1);
        g_adj[ps0] = cc.x;  g_adj[pd0] = rr.x;
        g_adj[ps1] = cc.y;  g_adj[pd1] = rr.y;
        g_adj[ps2] = cc.z;  g_adj[pd2] = rr.z;
        g_adj[ps3] = cc.w;  g_adj[pd3] = rr.w;
    } else {
        for (int e = e0; e < eh; e++) {
            int s = row[e], d = col[e];
            int ps = g_loc[s] + g_bpre[s >> 9] + atomicAdd(&g_rel[s], 1);
            g_adj[ps] = d;
            int pd = g_loc[d] + g_bpre[d >> 9] + atomicAdd(&g_rel[d], 1);
            g_adj[pd] = s;
        }
    }
}

// ---------------- K3: fused gather + final ------------------------------
// Warp per node. sub = lane&7, g = lane>>3. SINGLE gather stream: hd = dis*h.
//   dot: p = (hd_v . h_i) * invdis_v   (invdis in tdis.y; 1 mul post-reduce)
//   GCN: acc += hd_v (pure adds; Wg applied once per node via linearity)
// 4-deep pipeline: 16 neighbors in flight per warp.
__global__ __launch_bounds__(256, 5) void k_gather(
    const float* __restrict__ Wgm,
    const float* __restrict__ W1, const float* __restrict__ b1,
    const float* __restrict__ W2, const float* __restrict__ b2,
    const float* __restrict__ b_gcn,
    float* __restrict__ outp, float* __restrict__ repp, float* __restrict__ zoutp,
    int n)
{
    __shared__ float sW1[34 * HD];
    __shared__ float sWg[HD * HD];
    __shared__ float sb1[HD], sW2[HD], sb2s[1];
    __shared__ float sAcc[8][128];            // per-warp float4 transpose buffer

    int tid = threadIdx.x;
    for (int i = tid; i < 34 * HD; i += 256) sW1[i] = W1[i];
    for (int i = tid; i < HD * HD;  i += 256) sWg[i] = Wgm[i];
    if (tid < HD) { sb1[tid] = b1[tid]; sW2[tid] = W2[tid]; }
    if (tid == 0) sb2s[0] = b2[0];
    __syncthreads();

    int warp = tid >> 5, lane = tid & 31;
    int node = blockIdx.x * 8 + warp;
    if (node >= n) return;

    int sub = lane & 7;
    int g   = lane >> 3;
    unsigned gmask = 0xFFu << (g * 8);

    const float4* h4  = (const float4*)g_h;
    const float4* hd4 = (const float4*)g_hd;

    float4 hi = h4[(size_t)node * 8 + sub];
    int off = g_loc[node] + g_bpre[node >> 9];
    int cnt = g_cnt[node];

    float4 acc = make_float4(0.f, 0.f, 0.f, 0.f);  // sum dis_v * h_v
    float deno = 0.f, z = 0.f;

    int k = g;
    for (; k + 12 < cnt; k += 16) {
        int v0 = g_adj[off + k];
        int v1 = g_adj[off + k + 4];
        int v2 = g_adj[off + k + 8];
        int v3 = g_adj[off + k + 12];
        float4 d0 = hd4[(size_t)v0 * 8 + sub];
        float4 d1 = hd4[(size_t)v1 * 8 + sub];
        float4 d2 = hd4[(size_t)v2 * 8 + sub];
        float4 d3 = hd4[(size_t)v3 * 8 + sub];
        float2 t0 = g_tdis[v0];
        float2 t1 = g_tdis[v1];
        float2 t2 = g_tdis[v2];
        float2 t3 = g_tdis[v3];

        float p0 = hi.x*d0.x + hi.y*d0.y + hi.z*d0.z + hi.w*d0.w;
        float p1 = hi.x*d1.x + hi.y*d1.y + hi.z*d1.z + hi.w*d1.w;
        float p2 = hi.x*d2.x + hi.y*d2.y + hi.z*d2.z + hi.w*d2.w;
        float p3 = hi.x*d3.x + hi.y*d3.y + hi.z*d3.z + hi.w*d3.w;
        p0 += __shfl_xor_sync(gmask, p0, 1);
        p1 += __shfl_xor_sync(gmask, p1, 1);
        p2 += __shfl_xor_sync(gmask, p2, 1);
        p3 += __shfl_xor_sync(gmask, p3, 1);
        p0 += __shfl_xor_sync(gmask, p0, 2);
        p1 += __shfl_xor_sync(gmask, p1, 2);
        p2 += __shfl_xor_sync(gmask, p2, 2);
        p3 += __shfl_xor_sync(gmask, p3, 2);
        p0 += __shfl_xor_sync(gmask, p0, 4);
        p1 += __shfl_xor_sync(gmask, p1, 4);
        p2 += __shfl_xor_sync(gmask, p2, 4);
        p3 += __shfl_xor_sync(gmask, p3, 4);
        float a0 = __expf(p0 * t0.y);
        float a1 = __expf(p1 * t1.y);
        float a2 = __expf(p2 * t2.y);
        float a3 = __expf(p3 * t3.y);
        deno += (a0 + a1) + (a2 + a3);
        z = fmaf(a0, t0.x, z);
        z = fmaf(a1, t1.x, z);
        z = fmaf(a2, t2.x, z);
        z = fmaf(a3, t3.x, z);
        acc.x += (d0.x + d1.x) + (d2.x + d3.x);
        acc.y += (d0.y + d1.y) + (d2.y + d3.y);
        acc.z += (d0.z + d1.z) + (d2.z + d3.z);
        acc.w += (d0.w + d1.w) + (d2.w + d3.w);
    }
    for (; k < cnt; k += 4) {   // up to 3 remainder iterations per group
        int v = g_adj[off + k];
        float4 d = hd4[(size_t)v * 8 + sub];
        float2 td = g_tdis[v];
        float p = hi.x*d.x + hi.y*d.y + hi.z*d.z + hi.w*d.w;
        p += __shfl_xor_sync(gmask, p, 1);
        p += __shfl_xor_sync(gmask, p, 2);
        p += __shfl_xor_sync(gmask, p, 4);
        float a = __expf(p * td.y);
        deno += a;
        z = fmaf(a, td.x, z);
        acc.x += d.x; acc.y += d.y; acc.z += d.z; acc.w += d.w;
    }

    // deno/z: 8 lanes of each group hold identical partials -> warp tree
    // sum = 8 * (sum over groups); *0.125f is exact (power of two).
    #pragma unroll
    for (int o = 1; o < 32; o <<= 1) {
        deno += __shfl_xor_sync(0xffffffffu, deno, o);
        z    += __shfl_xor_sync(0xffffffffu, z,    o);
    }
    deno *= 0.125f; z *= 0.125f;

    // transpose acc (float4-per-lane) -> scalar-per-feature via smem
    sAcc[warp][lane * 4 + 0] = acc.x;
    sAcc[warp][lane * 4 + 1] = acc.y;
    sAcc[warp][lane * 4 + 2] = acc.z;
    sAcc[warp][lane * 4 + 3] = acc.w;
    __syncwarp();
    int slot = lane >> 2, comp = lane & 3;
    float aggj = 0.f;
    #pragma unroll
    for (int gg = 0; gg < 4; gg++)
        aggj += sAcc[warp][(gg * 8 + slot) * 4 + comp];
    // aggj = (sum_v dis_v h_v)[feature lane]; apply Wg: aggw = agg @ Wg
    float aggw = 0.f;
    #pragma unroll
    for (int kk = 0; kk < HD; kk++)
        aggw = fmaf(__shfl_sync(0xffffffffu, aggj, kk), sWg[kk * HD + lane], aggw);

    // ---- final head, inline ----
    // self-clean CSR state (after cnt consumed; epilogue recomputes dis)
    if (lane == 0) { g_cnt[node] = 0; g_rel[node] = 0; }
    float dis = rsqrtf((float)cnt + 1.0f);
    float hwj = g_hw[(size_t)node * HD + lane];   // h@Wg, UNscaled
    float hj  = g_h [(size_t)node * HD + lane];
    float gcn = dis * aggw + (dis * dis) * hwj + b_gcn[lane];
    float rep = hj + fmaxf(gcn, 0.f);
    if (repp) repp[(size_t)node * HD + lane] = rep;

    float2 tdn = g_tdis[node];
    float zi = z / (deno + 1e-8f);
    float ti = tdn.x;

    float accm = sb1[lane];
    #pragma unroll
    for (int kk = 0; kk < HD; kk++)
        accm = fmaf(__shfl_sync(0xffffffffu, rep, kk), sW1[kk * HD + lane], accm);
    accm = fmaf(ti, sW1[32 * HD + lane], accm);
    accm = fmaf(zi, sW1[33 * HD + lane], accm);
    accm = fmaxf(accm, 0.f);

    float o = accm * sW2[lane];
    #pragma unroll
    for (int offr = 16; offr > 0; offr >>= 1)
        o += __shfl_xor_sync(0xffffffffu, o, offr);
    if (lane == 0) outp[node] = o + sb2s[0];
    if (zoutp && lane == 1) zoutp[node] = zi;
}

// ---------------- host ----------------
extern "C" void kernel_launch(void* const* d_in, const int* in_sizes, int n_in,
                              void* d_out, int out_size)
{
    const float* x     = (const float*)d_in[0];
    const float* t     = (const float*)d_in[1];
    const int*   row   = (const int*)  d_in[2];
    const int*   col   = (const int*)  d_in[3];
    const float* W_emb = (const float*)d_in[4];
    const float* b_emb = (const float*)d_in[5];
    const float* W_gcn = (const float*)d_in[6];
    const float* b_gcn = (const float*)d_in[7];
    const float* W1    = (const float*)d_in[8];
    const float* b1    = (const float*)d_in[9];
    const float* W2    = (const float*)d_in[10];
    const float* b2    = (const float*)d_in[11];

    int n  = in_sizes[1];          // t has N elements
    int e2 = in_sizes[2];          // full directed edge count
    int eh = e2 / 2;               // symmetric half
    int nsb = (n + SCB - 1) / SCB;

    float* outp = (float*)d_out;
    bool full = (out_size == 34 * n);
    float* repp  = full ? outp + n      : nullptr;
    float* zoutp = full ? outp + 33 * n : nullptr;

    k_embed <<<(n + 15) / 16, 256>>>(x, W_emb, b_emb, W_gcn, row, col, n, eh); // idx 0
    k_scan  <<<nsb, SCB>>>(t, n, nsb);                                         // idx 1
    k_fill  <<<(eh + 1023) / 1024, 256>>>(row, col, eh);                       // idx 2
    k_gather<<<(n + 7) / 8, 256>>>(W_gcn, W1, b1, W2, b2, b_gcn, outp, repp, zoutp, n); // idx 3 (ncu)
}